// round 11
// baseline (speedup 1.0000x reference)
#include <cuda_runtime.h>
#include <math.h>

// ---------------------------------------------------------------------------
// EnBaseLayer (EGNN layer) for GB300 — algebraically restructured.
// Key identity: z@We1 = h[dst]@We1_hi + h[src]@We1_lo + feat@We1_f.
// The first two terms are NODE-scale GEMMs (precomputed once into g_h1/g_h2),
// so the per-EDGE layer-1 GEMM shrinks from K=280 to K=24.
// Total MACs: 46.4G -> 27.2G. Edge smem drops to ~108KB -> 2 CTAs/SM.
// Pipeline: zero(mi,dx) -> pre(H1,H2) -> edge -> node.
// (R9: resubmission of R8 source — the R8 bench died to a broker/container
//  failure before producing any result.)
// ---------------------------------------------------------------------------

#define NT   256      // threads per block
#define TE   64       // edges per block
#define TN   64       // nodes per block
#define HID  128
#define FS   24       // feat cols (20 gaussians + 4 edge_attr)
#define MS   132      // padded stride of 128-wide smem tiles
#define NZS  260      // padded stride of node [mi,h] tile
#define MAXN 50000
#define NPAD 50048    // 782*64, absorbs pre_kernel tail writes

__device__ float g_mi[NPAD * HID];
__device__ float g_h1[NPAD * HID];
__device__ float g_h2[NPAD * HID];
__device__ float g_dx[MAXN * 3];
__device__ float g_zero[HID];     // zero-initialized, never written

__device__ __forceinline__ float siluf(float v) {
    return v / (1.0f + __expf(-v));
}
__device__ __forceinline__ float sigmoidf_(float v) {
    return 1.0f / (1.0f + __expf(-v));
}
__device__ __forceinline__ void red_add_v4(float* p, float a, float b,
                                           float c, float d) {
    asm volatile("red.global.add.v4.f32 [%0], {%1, %2, %3, %4};"
                 :: "l"(p), "f"(a), "f"(b), "f"(c), "f"(d) : "memory");
}

// ---- packed f32x2 primitives (Blackwell) ----
__device__ __forceinline__ unsigned long long pack2(float v) {
    unsigned long long r;
    asm("mov.b64 %0, {%1, %1};" : "=l"(r) : "f"(v));
    return r;
}
__device__ __forceinline__ unsigned long long pack2f(float x, float y) {
    unsigned long long r;
    asm("mov.b64 %0, {%1, %2};" : "=l"(r) : "f"(x), "f"(y));
    return r;
}
__device__ __forceinline__ unsigned long long ffma2(
    unsigned long long a, unsigned long long b, unsigned long long c) {
    unsigned long long d;
    asm("fma.rn.f32x2 %0, %1, %2, %3;" : "=l"(d) : "l"(a), "l"(b), "l"(c));
    return d;
}
__device__ __forceinline__ float2 unpack2(unsigned long long v) {
    float2 f;
    asm("mov.b64 {%0, %1}, %2;" : "=f"(f.x), "=f"(f.y) : "l"(v));
    return f;
}

__global__ void zero_kernel(float* __restrict__ p, int n) {
    const int i = blockIdx.x * blockDim.x + threadIdx.x;
    const int stride = gridDim.x * blockDim.x;
    for (int k = i; k < n; k += stride) p[k] = 0.0f;
}

// Tiled GEMM: out[r][c] = act( sum_k s_in[r][k] * W[k][c] + b[c] )
// 64 rows x 128 cols, NT=256: thread (ty,tx) -> rows [4ty,4ty+4) x cols
// [4tx,+4) u [64+4tx,+4), packed f32x2 accumulators. out may be global.
template<int K, int KC, int SIN, bool ACT>
__device__ __forceinline__ void tile_gemm(
    const float* __restrict__ s_in, const float* __restrict__ W,
    const float* __restrict__ b, float* __restrict__ s_out, int out_stride,
    float* __restrict__ s_w, int tid)
{
    const int ty = tid >> 4;
    const int tx = tid & 15;
    const int r0 = 4 * ty;
    const int c0 = 4 * tx;
    unsigned long long acc[4][4];
#pragma unroll
    for (int i = 0; i < 4; i++)
#pragma unroll
        for (int j = 0; j < 4; j++) acc[i][j] = 0ull;

    for (int k0 = 0; k0 < K; k0 += KC) {
        __syncthreads();  // prior consumers of s_w / producers of s_in done
        {
            const float4* Wv = (const float4*)(W + (size_t)k0 * HID);
            float4* sv = (float4*)s_w;
#pragma unroll
            for (int i = tid; i < KC * HID / 4; i += NT) sv[i] = Wv[i];
        }
        __syncthreads();
#pragma unroll 2
        for (int kk = 0; kk < KC; kk += 4) {
            float4 zv[4];
#pragma unroll
            for (int i = 0; i < 4; i++)
                zv[i] = *(const float4*)(s_in + (r0 + i) * SIN + k0 + kk);
            const float* zf = (const float*)zv;
#pragma unroll
            for (int u = 0; u < 4; u++) {
                const int k = kk + u;
                const ulonglong2 wA = *(const ulonglong2*)(s_w + k * HID + c0);
                const ulonglong2 wB = *(const ulonglong2*)(s_w + k * HID + c0 + 64);
#pragma unroll
                for (int i = 0; i < 4; i++) {
                    const unsigned long long zz = pack2(zf[i * 4 + u]);
                    acc[i][0] = ffma2(zz, wA.x, acc[i][0]);
                    acc[i][1] = ffma2(zz, wA.y, acc[i][1]);
                    acc[i][2] = ffma2(zz, wB.x, acc[i][2]);
                    acc[i][3] = ffma2(zz, wB.y, acc[i][3]);
                }
            }
        }
    }
    const float4 ba = *(const float4*)(b + c0);
    const float4 bb = *(const float4*)(b + c0 + 64);
#pragma unroll
    for (int i = 0; i < 4; i++) {
        const float2 p0 = unpack2(acc[i][0]);
        const float2 p1 = unpack2(acc[i][1]);
        const float2 p2 = unpack2(acc[i][2]);
        const float2 p3 = unpack2(acc[i][3]);
        float v[8];
        v[0] = p0.x + ba.x; v[1] = p0.y + ba.y;
        v[2] = p1.x + ba.z; v[3] = p1.y + ba.w;
        v[4] = p2.x + bb.x; v[5] = p2.y + bb.y;
        v[6] = p3.x + bb.z; v[7] = p3.y + bb.w;
        if (ACT) {
#pragma unroll
            for (int j = 0; j < 8; j++) v[j] = siluf(v[j]);
        }
        *(float4*)(s_out + (size_t)(r0 + i) * out_stride + c0) =
            make_float4(v[0], v[1], v[2], v[3]);
        *(float4*)(s_out + (size_t)(r0 + i) * out_stride + c0 + 64) =
            make_float4(v[4], v[5], v[6], v[7]);
    }
}

// smem sizes (floats)
#define SW_F   (64*HID)
#define PRE_SMEM_F  (TN*MS + SW_F)
#define EDGE_SMEM_F (TE*FS + SW_F + TE*MS + TE*MS + TE*3 + TE + TE + TE + TE + TE)
#define NODE_SMEM_F (TN*NZS + SW_F + TN*MS)

// ---- pre: H1 = h @ We1[0:128], H2 = h @ We1[128:256] ----
__global__ __launch_bounds__(NT, 1)
void pre_kernel(const float* __restrict__ h, const float* __restrict__ We1,
                int N)
{
    extern __shared__ float sm[];
    float* s_in = sm;                 // TN*MS
    float* s_w  = s_in + TN * MS;     // 64*HID
    const int tid = threadIdx.x;
    const int n0  = blockIdx.x * TN;

    for (int idx = tid; idx < TN * 32; idx += NT) {
        const int r = idx >> 5, q = idx & 31;
        int n = n0 + r; if (n >= N) n = N - 1;   // clamp reads; pad writes OK
        *(float4*)(s_in + r * MS + 4 * q) =
            *(const float4*)(h + (size_t)n * HID + 4 * q);
    }
    // tile_gemm's leading sync orders the gather before first use
    tile_gemm<HID, 64, MS, false>(s_in, We1, g_zero,
                                  g_h1 + (size_t)n0 * HID, HID, s_w, tid);
    tile_gemm<HID, 64, MS, false>(s_in, We1 + HID * HID, g_zero,
                                  g_h2 + (size_t)n0 * HID, HID, s_w, tid);
}

__global__ __launch_bounds__(NT, 2)
void edge_kernel(const float* __restrict__ x,
                 const int* __restrict__ eidx,
                 const float* __restrict__ eattr,
                 const float* __restrict__ We1, const float* __restrict__ be1,
                 const float* __restrict__ We2, const float* __restrict__ be2,
                 const float* __restrict__ Winf, const float* __restrict__ binf,
                 const float* __restrict__ Wx1, const float* __restrict__ bx1,
                 const float* __restrict__ Wx2,
                 int E)
{
    extern __shared__ float sm[];
    float* s_f   = sm;                    // TE*FS : [d_feat|eattr]
    float* s_w   = s_f + TE * FS;         // 64*HID: weight staging (>= 24*HID)
    float* s_a   = s_w + SW_F;            // TE*MS : layer-1 out / hx
    float* s_m   = s_a + TE * MS;         // TE*MS : mij
    float* s_rel = s_m + TE * MS;         // TE*3
    float* s_d   = s_rel + TE * 3;        // TE
    float* s_e   = s_d + TE;              // TE : eij
    float* s_g   = s_e + TE;              // TE : xg
    int*   s_dst = (int*)(s_g + TE);      // TE
    int*   s_src = (int*)(s_dst + TE);    // TE

    const int tid = threadIdx.x;
    const int e0  = blockIdx.x * TE;

    // ---- per-edge meta: indices, rel_x, distance, gaussian smearing ----
    if (tid < TE) {
        const int e = e0 + tid;
        int src = 0, dst = 0;
        float d = 1.0f, rx = 0.f, ry = 0.f, rz = 0.f;
        if (e < E) {
            src = eidx[e];          // int32 (JAX x64 disabled)
            dst = eidx[E + e];
            rx = x[dst * 3 + 0] - x[src * 3 + 0];
            ry = x[dst * 3 + 1] - x[src * 3 + 1];
            rz = x[dst * 3 + 2] - x[src * 3 + 2];
            d  = sqrtf(rx * rx + ry * ry + rz * rz + 1e-8f);
        }
        s_src[tid] = src;
        s_dst[tid] = dst;
        s_rel[tid * 3 + 0] = rx;
        s_rel[tid * 3 + 1] = ry;
        s_rel[tid * 3 + 2] = rz;
        s_d[tid] = d;
        const float step  = 10.0f / 19.0f;
        const float coeff = -0.5f / (step * step);
#pragma unroll
        for (int g = 0; g < 20; g++) {
            const float t = d - step * (float)g;
            s_f[tid * FS + g] = __expf(coeff * t * t);
        }
        float4 ea = make_float4(0.f, 0.f, 0.f, 0.f);
        if (e < E) ea = *(const float4*)(eattr + (size_t)e * 4);
        s_f[tid * FS + 20] = ea.x;
        s_f[tid * FS + 21] = ea.y;
        s_f[tid * FS + 22] = ea.z;
        s_f[tid * FS + 23] = ea.w;
    }
    // ---- stage feat weights We1[256:280] (24 x 128) into s_w ----
    {
        const float4* Wv = (const float4*)(We1 + 256 * HID);
        float4* sv = (float4*)s_w;
        for (int i = tid; i < FS * HID / 4; i += NT) sv[i] = Wv[i];
    }
    __syncthreads();   // s_f, s_dst/src, s_w(W24) all visible

    const int ty = tid >> 4;
    const int tx = tid & 15;
    const int r0 = 4 * ty;
    const int c0 = 4 * tx;

    // ---- layer 1: acc = H1[dst] + H2[src]; then += feat @ W24 ----
    {
        unsigned long long acc[4][4];
#pragma unroll
        for (int i = 0; i < 4; i++) {
            const size_t dst = (size_t)s_dst[r0 + i] * HID;
            const size_t src = (size_t)s_src[r0 + i] * HID;
            const float4 a1 = *(const float4*)(g_h1 + dst + c0);
            const float4 a2 = *(const float4*)(g_h2 + src + c0);
            const float4 b1 = *(const float4*)(g_h1 + dst + c0 + 64);
            const float4 b2 = *(const float4*)(g_h2 + src + c0 + 64);
            acc[i][0] = pack2f(a1.x + a2.x, a1.y + a2.y);
            acc[i][1] = pack2f(a1.z + a2.z, a1.w + a2.w);
            acc[i][2] = pack2f(b1.x + b2.x, b1.y + b2.y);
            acc[i][3] = pack2f(b1.z + b2.z, b1.w + b2.w);
        }
#pragma unroll
        for (int kk = 0; kk < FS; kk += 4) {
            float4 zv[4];
#pragma unroll
            for (int i = 0; i < 4; i++)
                zv[i] = *(const float4*)(s_f + (r0 + i) * FS + kk);
            const float* zf = (const float*)zv;
#pragma unroll
            for (int u = 0; u < 4; u++) {
                const int k = kk + u;
                const ulonglong2 wA = *(const ulonglong2*)(s_w + k * HID + c0);
                const ulonglong2 wB = *(const ulonglong2*)(s_w + k * HID + c0 + 64);
#pragma unroll
                for (int i = 0; i < 4; i++) {
                    const unsigned long long zz = pack2(zf[i * 4 + u]);
                    acc[i][0] = ffma2(zz, wA.x, acc[i][0]);
                    acc[i][1] = ffma2(zz, wA.y, acc[i][1]);
                    acc[i][2] = ffma2(zz, wB.x, acc[i][2]);
                    acc[i][3] = ffma2(zz, wB.y, acc[i][3]);
                }
            }
        }
        const float4 ba = *(const float4*)(be1 + c0);
        const float4 bb = *(const float4*)(be1 + c0 + 64);
#pragma unroll
        for (int i = 0; i < 4; i++) {
            const float2 p0 = unpack2(acc[i][0]);
            const float2 p1 = unpack2(acc[i][1]);
            const float2 p2 = unpack2(acc[i][2]);
            const float2 p3 = unpack2(acc[i][3]);
            *(float4*)(s_a + (r0 + i) * MS + c0) = make_float4(
                siluf(p0.x + ba.x), siluf(p0.y + ba.y),
                siluf(p1.x + ba.z), siluf(p1.y + ba.w));
            *(float4*)(s_a + (r0 + i) * MS + c0 + 64) = make_float4(
                siluf(p2.x + bb.x), siluf(p2.y + bb.y),
                siluf(p3.x + bb.z), siluf(p3.y + bb.w));
        }
    }

    // ---- edge MLP layer 2: mij = silu(a1 @ We2 + be2) -> s_m ----
    tile_gemm<HID, 64, MS, true>(s_a, We2, be2, s_m, MS, s_w, tid);
    __syncthreads();

    // ---- eij = sigmoid(mij . Winf + binf): 4 threads per edge + shfl ----
    {
        const int e   = tid >> 2;
        const int sub = tid & 3;
        const int kb  = sub * 32;
        float s = 0.0f;
#pragma unroll
        for (int i = 0; i < 32; i++)
            s = fmaf(s_m[e * MS + kb + i], __ldg(Winf + kb + i), s);
        s += __shfl_xor_sync(0xffffffffu, s, 2);
        s += __shfl_xor_sync(0xffffffffu, s, 1);
        if (sub == 0) {
            const bool valid = (e0 + e) < E;
            s_e[e] = valid ? sigmoidf_(s + __ldg(binf)) : 0.0f;
        }
    }

    // ---- coord head: hx = silu(mij @ Wx1 + bx1) -> s_a (reuse) ----
    tile_gemm<HID, 64, MS, true>(s_m, Wx1, bx1, s_a, MS, s_w, tid);
    __syncthreads();

    // ---- xg = tanh(hx . Wx2) ----
    {
        const int e   = tid >> 2;
        const int sub = tid & 3;
        const int kb  = sub * 32;
        float s = 0.0f;
#pragma unroll
        for (int i = 0; i < 32; i++)
            s = fmaf(s_a[e * MS + kb + i], __ldg(Wx2 + kb + i), s);
        s += __shfl_xor_sync(0xffffffffu, s, 2);
        s += __shfl_xor_sync(0xffffffffu, s, 1);
        if (sub == 0) {
            const bool valid = (e0 + e) < E;
            s_g[e] = valid ? tanhf(s) : 0.0f;
        }
    }
    __syncthreads();

    // ---- scatter: mi[dst] += mij * eij  (vector red) ----
    for (int idx = tid; idx < TE * 32; idx += NT) {
        const int e = idx >> 5, q = idx & 31;
        const float se = s_e[e];
        const float* mrow = s_m + e * MS + 4 * q;
        float* dstp = g_mi + (size_t)s_dst[e] * HID + 4 * q;
        red_add_v4(dstp, mrow[0] * se, mrow[1] * se, mrow[2] * se, mrow[3] * se);
    }
    // ---- scatter: dx[dst] += rel_x / (d+1) * xg ----
    if (tid < TE) {
        const float fac = s_g[tid] / (s_d[tid] + 1.0f);
        const int dst = s_dst[tid];
#pragma unroll
        for (int c = 0; c < 3; c++)
            atomicAdd(&g_dx[(size_t)dst * 3 + c], s_rel[tid * 3 + c] * fac);
    }
}

__global__ __launch_bounds__(NT, 1)
void node_kernel(const float* __restrict__ h, const float* __restrict__ x,
                 const float* __restrict__ mask,
                 const float* __restrict__ Wn1, const float* __restrict__ bn1,
                 const float* __restrict__ Wn2, const float* __restrict__ bn2,
                 float* __restrict__ out_h, float* __restrict__ out_x, int N)
{
    extern __shared__ float sm[];
    float* s_nz = sm;                   // TN*NZS : [mi | h]
    float* s_w  = s_nz + TN * NZS;      // 64*HID
    float* s_a  = s_w + SW_F;           // TN*MS

    const int tid = threadIdx.x;
    const int n0  = blockIdx.x * TN;

    for (int idx = tid; idx < TN * 32; idx += NT) {
        const int r = idx >> 5, q = idx & 31;
        const int n = n0 + r;
        float4 vm = make_float4(0.f, 0.f, 0.f, 0.f);
        float4 vh = vm;
        if (n < N) {
            vm = *(const float4*)(g_mi + (size_t)n * HID + 4 * q);
            vh = *(const float4*)(h + (size_t)n * HID + 4 * q);
        }
        *(float4*)(s_nz + r * NZS + 4 * q)       = vm;
        *(float4*)(s_nz + r * NZS + HID + 4 * q) = vh;
    }

    tile_gemm<2 * HID, 64, NZS, true>(s_nz, Wn1, bn1, s_a, MS, s_w, tid);
    tile_gemm<HID, 64, MS, false>(s_a, Wn2, bn2, s_nz, NZS, s_w, tid);
    __syncthreads();

    for (int idx = tid; idx < TN * 32; idx += NT) {
        const int r = idx >> 5, q = idx & 31;
        const int n = n0 + r;
        if (n < N) {
            const float4 vh = *(const float4*)(h + (size_t)n * HID + 4 * q);
            const float4 vr = *(const float4*)(s_nz + r * NZS + 4 * q);
            *(float4*)(out_h + (size_t)n * HID + 4 * q) =
                make_float4(vh.x + vr.x, vh.y + vr.y, vh.z + vr.z, vh.w + vr.w);
        }
    }
    if (tid < TN) {
        const int n = n0 + tid;
        if (n < N) {
            const float m = mask[n];
#pragma unroll
            for (int c = 0; c < 3; c++)
                out_x[(size_t)n * 3 + c] =
                    x[(size_t)n * 3 + c] + g_dx[(size_t)n * 3 + c] * m;
        }
    }
}

extern "C" void kernel_launch(void* const* d_in, const int* in_sizes, int n_in,
                              void* d_out, int out_size)
{
    const float* h     = (const float*)d_in[0];
    const float* x     = (const float*)d_in[1];
    const int*   eidx  = (const int*)d_in[2];   // int32 (JAX x64 disabled)
    const float* mask  = (const float*)d_in[3];
    const float* eattr = (const float*)d_in[4];
    const float* We1   = (const float*)d_in[5];
    const float* be1   = (const float*)d_in[6];
    const float* We2   = (const float*)d_in[7];
    const float* be2   = (const float*)d_in[8];
    const float* Winf  = (const float*)d_in[9];
    const float* binf  = (const float*)d_in[10];
    const float* Wx1   = (const float*)d_in[11];
    const float* bx1   = (const float*)d_in[12];
    const float* Wx2   = (const float*)d_in[13];
    const float* Wn1   = (const float*)d_in[14];
    const float* bn1   = (const float*)d_in[15];
    const float* Wn2   = (const float*)d_in[16];
    const float* bn2   = (const float*)d_in[17];

    const int N = in_sizes[0] / HID;
    const int E = in_sizes[2] / 2;
    float* out   = (float*)d_out;
    float* out_h = out;
    float* out_x = out + (size_t)N * HID;

    void* mi_ptr = nullptr;
    void* dx_ptr = nullptr;
    cudaGetSymbolAddress(&mi_ptr, g_mi);
    cudaGetSymbolAddress(&dx_ptr, g_dx);
    zero_kernel<<<592, 256>>>((float*)mi_ptr, N * HID);
    zero_kernel<<<64, 256>>>((float*)dx_ptr, N * 3);

    const size_t pre_smem  = (size_t)PRE_SMEM_F * sizeof(float);
    const size_t edge_smem = (size_t)EDGE_SMEM_F * sizeof(float);
    const size_t node_smem = (size_t)NODE_SMEM_F * sizeof(float);
    cudaFuncSetAttribute(pre_kernel,
                         cudaFuncAttributeMaxDynamicSharedMemorySize,
                         (int)pre_smem);
    cudaFuncSetAttribute(edge_kernel,
                         cudaFuncAttributeMaxDynamicSharedMemorySize,
                         (int)edge_smem);
    cudaFuncSetAttribute(node_kernel,
                         cudaFuncAttributeMaxDynamicSharedMemorySize,
                         (int)node_smem);

    const int nb = (N + TN - 1) / TN;
    pre_kernel<<<nb, NT, pre_smem>>>(h, We1, N);

    const int eb = (E + TE - 1) / TE;
    edge_kernel<<<eb, NT, edge_smem>>>(x, eidx, eattr,
                                       We1, be1, We2, be2,
                                       Winf, binf, Wx1, bx1, Wx2, E);

    node_kernel<<<nb, NT, node_smem>>>(h, x, mask, Wn1, bn1, Wn2, bn2,
                                       out_h, out_x, N);
}

// round 13
// speedup vs baseline: 1.0095x; 1.0095x over previous
#include <cuda_runtime.h>
#include <math.h>
#include <stdint.h>

// ---------------------------------------------------------------------------
// EnBaseLayer (EGNN) GB300 — fp32 FFMA2 with cp.async double-buffered weight
// staging. tcgen05 is unusable (harness ptxas targets sm_103, not sm_103a:
// tcgen05.ld/wait are 'a'-only), so the play is hiding all staging latency
// behind the FMA pipe. Pipeline: zero(mi,dx) -> pre(H1,H2) -> edge -> node.
// Edge algebra (R10 win): z@We1 = H1[dst] + H2[src] + feat@W24.
// ---------------------------------------------------------------------------

#define NT   256
#define TE   64
#define TN   64
#define HID  128
#define FS   24
#define MS   132
#define NZS  260
#define KC   32       // pipelined chunk depth (rows of W per stage)
#define MAXN 50000
#define NPAD 50048

__device__ float g_mi[NPAD * HID];
__device__ float g_h1[NPAD * HID];
__device__ float g_h2[NPAD * HID];
__device__ float g_dx[MAXN * 3];
__device__ float g_zero[HID];

__device__ __forceinline__ float siluf(float v){ return v/(1.0f+__expf(-v)); }
__device__ __forceinline__ float sigmoidf_(float v){ return 1.0f/(1.0f+__expf(-v)); }
__device__ __forceinline__ void red_add_v4(float* p, float a, float b, float c, float d){
    asm volatile("red.global.add.v4.f32 [%0], {%1, %2, %3, %4};"
                 :: "l"(p), "f"(a), "f"(b), "f"(c), "f"(d) : "memory");
}
__device__ __forceinline__ unsigned long long pack2(float v){
    unsigned long long r; asm("mov.b64 %0, {%1, %1};" : "=l"(r) : "f"(v)); return r;
}
__device__ __forceinline__ unsigned long long pack2f(float x, float y){
    unsigned long long r; asm("mov.b64 %0, {%1, %2};" : "=l"(r) : "f"(x), "f"(y)); return r;
}
__device__ __forceinline__ unsigned long long ffma2(unsigned long long a,
    unsigned long long b, unsigned long long c){
    unsigned long long d;
    asm("fma.rn.f32x2 %0, %1, %2, %3;" : "=l"(d) : "l"(a), "l"(b), "l"(c));
    return d;
}
__device__ __forceinline__ float2 unpack2(unsigned long long v){
    float2 f; asm("mov.b64 {%0, %1}, %2;" : "=f"(f.x), "=f"(f.y) : "l"(v)); return f;
}
__device__ __forceinline__ uint32_t smem_u32(const void* p){
    uint32_t a;
    asm("{ .reg .u64 t; cvta.to.shared.u64 t, %1; cvt.u32.u64 %0, t; }" : "=r"(a) : "l"(p));
    return a;
}
// ---- cp.async (Ampere+; family-safe on sm_103) ----
__device__ __forceinline__ void cp16(uint32_t saddr, const void* g){
    asm volatile("cp.async.cg.shared.global [%0], [%1], 16;" :: "r"(saddr), "l"(g));
}
#define CP_COMMIT() asm volatile("cp.async.commit_group;" ::: "memory")
template<int N> __device__ __forceinline__ void cp_wait(){
    asm volatile("cp.async.wait_group %0;" :: "n"(N) : "memory");
}
// stage `units` 16B-chunks of W into smem buf (all NT threads)
__device__ __forceinline__ void stage_chunk(float* buf, const float* W, int units, int tid){
    const uint32_t sb = smem_u32(buf);
    const char* g = (const char*)W;
    for (int i = tid; i < units; i += NT) cp16(sb + 16u*i, g + 16u*i);
}

__global__ void zero_kernel(float* __restrict__ p, int n){
    const int i = blockIdx.x*blockDim.x + threadIdx.x, s = gridDim.x*blockDim.x;
    for (int k = i; k < n; k += s) p[k] = 0.0f;
}

// Pipelined tiled GEMM: 64 rows x 128 cols, NT=256, packed-f32x2 accumulators.
// Chunk c lives in buf[(c+P0)&1]; caller pre-issues chunk 0 into buf[P0].
// One __syncthreads per chunk: wait(all cp done) -> sync -> stage next -> compute.
template<int K, int SIN, bool ACT, int P0>
__device__ __forceinline__ void gemm_pipe(
    const float* s_in, const float* __restrict__ W, const float* __restrict__ b,
    float* s_out, int out_stride, float* buf0, float* buf1, int tid)
{
    constexpr int NC = K / KC;
    const int ty = tid >> 4, tx = tid & 15;
    const int r0 = 4*ty, c0 = 4*tx;
    unsigned long long acc[4][4];
#pragma unroll
    for (int i=0;i<4;i++)
#pragma unroll
        for (int j=0;j<4;j++) acc[i][j]=0ull;
    float* bufs[2] = {buf0, buf1};
    for (int c = 0; c < NC; c++){
        cp_wait<0>();
        __syncthreads();
        if (c + 1 < NC){
            stage_chunk(bufs[(c+1+P0)&1], W + (size_t)(c+1)*KC*HID, KC*32, tid);
            CP_COMMIT();
        }
        const float* s_w = bufs[(c+P0)&1];
        const int k0 = c*KC;
#pragma unroll 2
        for (int kk=0; kk<KC; kk+=4){
            float4 zv[4];
#pragma unroll
            for (int i=0;i<4;i++) zv[i] = *(const float4*)(s_in + (r0+i)*SIN + k0 + kk);
            const float* zf = (const float*)zv;
#pragma unroll
            for (int u=0;u<4;u++){
                const int k = kk+u;
                const ulonglong2 wA = *(const ulonglong2*)(s_w + k*HID + c0);
                const ulonglong2 wB = *(const ulonglong2*)(s_w + k*HID + c0 + 64);
#pragma unroll
                for (int i=0;i<4;i++){
                    const unsigned long long zz = pack2(zf[i*4+u]);
                    acc[i][0]=ffma2(zz,wA.x,acc[i][0]); acc[i][1]=ffma2(zz,wA.y,acc[i][1]);
                    acc[i][2]=ffma2(zz,wB.x,acc[i][2]); acc[i][3]=ffma2(zz,wB.y,acc[i][3]);
                }
            }
        }
    }
    const float4 ba=*(const float4*)(b+c0), bb=*(const float4*)(b+c0+64);
#pragma unroll
    for (int i=0;i<4;i++){
        const float2 p0=unpack2(acc[i][0]), p1=unpack2(acc[i][1]);
        const float2 p2=unpack2(acc[i][2]), p3=unpack2(acc[i][3]);
        float v[8]={p0.x+ba.x,p0.y+ba.y,p1.x+ba.z,p1.y+ba.w,
                    p2.x+bb.x,p2.y+bb.y,p3.x+bb.z,p3.y+bb.w};
        if (ACT){
#pragma unroll
            for (int j=0;j<8;j++) v[j]=siluf(v[j]); }
        *(float4*)(s_out+(size_t)(r0+i)*out_stride+c0)    = make_float4(v[0],v[1],v[2],v[3]);
        *(float4*)(s_out+(size_t)(r0+i)*out_stride+c0+64) = make_float4(v[4],v[5],v[6],v[7]);
    }
}

// smem sizes (floats)
#define BUF_F  (KC*HID)                       // 4096 per buffer
#define PRE_SMEM_F  (TN*MS + 2*BUF_F)
#define EDGE_SMEM_F (TE*FS + 2*BUF_F + TE*MS + TE*MS + TE*3 + 5*TE)
#define NODE_SMEM_F (TN*NZS + 2*BUF_F + TN*MS)

__global__ __launch_bounds__(NT, 1)
void pre_kernel(const float* __restrict__ h, const float* __restrict__ We1, int N){
    extern __shared__ float smf[];
    float* s_in = smf;                 // TN*MS
    float* buf0 = s_in + TN*MS;        // BUF_F
    float* buf1 = buf0 + BUF_F;        // BUF_F
    const int tid = threadIdx.x, n0 = blockIdx.x*TN;
    // pre-issue chunk0 of We1[0:128]
    stage_chunk(buf0, We1, KC*32, tid); CP_COMMIT();
    for (int idx = tid; idx < TN*32; idx += NT){
        const int r = idx>>5, q = idx&31; int n = n0+r; if (n>=N) n=N-1;
        *(float4*)(s_in + r*MS + 4*q) = *(const float4*)(h + (size_t)n*HID + 4*q);
    }
    gemm_pipe<HID, MS, false, 0>(s_in, We1, g_zero,
                                 g_h1 + (size_t)n0*HID, HID, buf0, buf1, tid);
    // last chunk computed from buf1 -> buf0 free; pre-issue We1[128:256] c0
    stage_chunk(buf0, We1 + HID*HID, KC*32, tid); CP_COMMIT();
    gemm_pipe<HID, MS, false, 0>(s_in, We1 + HID*HID, g_zero,
                                 g_h2 + (size_t)n0*HID, HID, buf0, buf1, tid);
}

__global__ __launch_bounds__(NT, 2)
void edge_kernel(const float* __restrict__ x, const int* __restrict__ eidx,
                 const float* __restrict__ eattr,
                 const float* __restrict__ We1, const float* __restrict__ be1,
                 const float* __restrict__ We2, const float* __restrict__ be2,
                 const float* __restrict__ Winf, const float* __restrict__ binf,
                 const float* __restrict__ Wx1, const float* __restrict__ bx1,
                 const float* __restrict__ Wx2, int E)
{
    extern __shared__ float smf[];
    float* s_f   = smf;                  // TE*FS
    float* buf0  = s_f + TE*FS;          // BUF_F  (holds W24 first)
    float* buf1  = buf0 + BUF_F;         // BUF_F
    float* s_a   = buf1 + BUF_F;         // TE*MS
    float* s_m   = s_a + TE*MS;          // TE*MS
    float* s_rel = s_m + TE*MS;          // TE*3
    float* s_d   = s_rel + TE*3;         // TE
    float* s_e   = s_d + TE;             // TE
    float* s_g   = s_e + TE;             // TE
    int*   s_dst = (int*)(s_g + TE);     // TE
    int*   s_src = (int*)(s_dst + TE);   // TE

    const int tid = threadIdx.x;
    const int e0  = blockIdx.x * TE;

    // stage W24 = We1[256:280] (24x128) into buf0 ASAP
    stage_chunk(buf0, We1 + 256*HID, 768, tid); CP_COMMIT();

    // ---- meta: indices, rel_x, d, gaussians, edge_attr ----
    if (tid < TE){
        const int e = e0 + tid;
        int src = 0, dst = 0;
        float d = 1.0f, rx=0.f, ry=0.f, rz=0.f;
        if (e < E){
            src = eidx[e];          // int32 (JAX x64 disabled)
            dst = eidx[E + e];
            rx = x[dst*3+0]-x[src*3+0];
            ry = x[dst*3+1]-x[src*3+1];
            rz = x[dst*3+2]-x[src*3+2];
            d  = sqrtf(rx*rx + ry*ry + rz*rz + 1e-8f);
        }
        s_src[tid]=src; s_dst[tid]=dst;
        s_rel[tid*3+0]=rx; s_rel[tid*3+1]=ry; s_rel[tid*3+2]=rz;
        s_d[tid]=d;
        const float step = 10.0f/19.0f, coeff = -0.5f/(step*step);
#pragma unroll
        for (int g=0; g<20; g++){
            const float t = d - step*(float)g;
            s_f[tid*FS + g] = __expf(coeff*t*t);
        }
        float4 ea = make_float4(0.f,0.f,0.f,0.f);
        if (e < E) ea = *(const float4*)(eattr + (size_t)e*4);
        s_f[tid*FS+20]=ea.x; s_f[tid*FS+21]=ea.y;
        s_f[tid*FS+22]=ea.z; s_f[tid*FS+23]=ea.w;
    }
    __syncthreads();   // meta + s_f visible

    const int ty = tid >> 4, tx = tid & 15;
    const int r0 = 4*ty, c0 = 4*tx;

    // ---- layer 1: acc = H1[dst]+H2[src] (gathers overlap W24 cp.async) ----
    unsigned long long acc[4][4];
#pragma unroll
    for (int i=0;i<4;i++){
        const size_t dst = (size_t)s_dst[r0+i]*HID;
        const size_t src = (size_t)s_src[r0+i]*HID;
        const float4 a1 = *(const float4*)(g_h1 + dst + c0);
        const float4 a2 = *(const float4*)(g_h2 + src + c0);
        const float4 b1 = *(const float4*)(g_h1 + dst + c0 + 64);
        const float4 b2 = *(const float4*)(g_h2 + src + c0 + 64);
        acc[i][0]=pack2f(a1.x+a2.x, a1.y+a2.y);
        acc[i][1]=pack2f(a1.z+a2.z, a1.w+a2.w);
        acc[i][2]=pack2f(b1.x+b2.x, b1.y+b2.y);
        acc[i][3]=pack2f(b1.z+b2.z, b1.w+b2.w);
    }
    // pre-issue We2 chunk0 -> buf1 (overlaps K24 compute)
    stage_chunk(buf1, We2, KC*32, tid); CP_COMMIT();
    cp_wait<1>();      // W24 (FIFO-first) complete; We2c0 may still fly
    __syncthreads();
    // K24 compute from buf0
#pragma unroll
    for (int kk=0; kk<FS; kk+=4){
        float4 zv[4];
#pragma unroll
        for (int i=0;i<4;i++) zv[i] = *(const float4*)(s_f + (r0+i)*FS + kk);
        const float* zf = (const float*)zv;
#pragma unroll
        for (int u=0;u<4;u++){
            const int k = kk+u;
            const ulonglong2 wA = *(const ulonglong2*)(buf0 + k*HID + c0);
            const ulonglong2 wB = *(const ulonglong2*)(buf0 + k*HID + c0 + 64);
#pragma unroll
            for (int i=0;i<4;i++){
                const unsigned long long zz = pack2(zf[i*4+u]);
                acc[i][0]=ffma2(zz,wA.x,acc[i][0]); acc[i][1]=ffma2(zz,wA.y,acc[i][1]);
                acc[i][2]=ffma2(zz,wB.x,acc[i][2]); acc[i][3]=ffma2(zz,wB.y,acc[i][3]);
            }
        }
    }
    {
        const float4 ba=*(const float4*)(be1+c0), bb=*(const float4*)(be1+c0+64);
#pragma unroll
        for (int i=0;i<4;i++){
            const float2 p0=unpack2(acc[i][0]), p1=unpack2(acc[i][1]);
            const float2 p2=unpack2(acc[i][2]), p3=unpack2(acc[i][3]);
            *(float4*)(s_a+(r0+i)*MS+c0) = make_float4(
                siluf(p0.x+ba.x), siluf(p0.y+ba.y), siluf(p1.x+ba.z), siluf(p1.y+ba.w));
            *(float4*)(s_a+(r0+i)*MS+c0+64) = make_float4(
                siluf(p2.x+bb.x), siluf(p2.y+bb.y), siluf(p3.x+bb.z), siluf(p3.y+bb.w));
        }
    }

    // ---- layer 2: mij = silu(a1 @ We2 + be2); chunk0 pre-staged in buf1 ----
    gemm_pipe<HID, MS, true, 1>(s_a, We2, be2, s_m, MS, buf0, buf1, tid);
    // pre-issue Wx1 chunk0 -> buf1 (layer2 stragglers only read buf0)
    stage_chunk(buf1, Wx1, KC*32, tid); CP_COMMIT();
    __syncthreads();   // s_m visible to all

    // ---- eij = sigmoid(mij . Winf + binf): 4 threads/edge + shfl ----
    {
        const int e = tid>>2, sub = tid&3, kb = sub*32;
        float s = 0.0f;
#pragma unroll
        for (int i=0;i<32;i++) s = fmaf(s_m[e*MS+kb+i], __ldg(Winf+kb+i), s);
        s += __shfl_xor_sync(0xffffffffu, s, 2);
        s += __shfl_xor_sync(0xffffffffu, s, 1);
        if (sub == 0){
            const bool valid = (e0 + e) < E;
            s_e[e] = valid ? sigmoidf_(s + __ldg(binf)) : 0.0f;
        }
    }

    // ---- coord head: hx = silu(mij @ Wx1 + bx1) ----
    gemm_pipe<HID, MS, true, 1>(s_m, Wx1, bx1, s_a, MS, buf0, buf1, tid);
    __syncthreads();

    // ---- xg = tanh(hx . Wx2) ----
    {
        const int e = tid>>2, sub = tid&3, kb = sub*32;
        float s = 0.0f;
#pragma unroll
        for (int i=0;i<32;i++) s = fmaf(s_a[e*MS+kb+i], __ldg(Wx2+kb+i), s);
        s += __shfl_xor_sync(0xffffffffu, s, 2);
        s += __shfl_xor_sync(0xffffffffu, s, 1);
        if (sub == 0){
            const bool valid = (e0 + e) < E;
            s_g[e] = valid ? tanhf(s) : 0.0f;
        }
    }
    __syncthreads();

    // ---- scatter: mi[dst] += mij * eij ----
    for (int idx = tid; idx < TE*32; idx += NT){
        const int e = idx>>5, q = idx&31;
        const float se = s_e[e];
        const float* mrow = s_m + e*MS + 4*q;
        float* dstp = g_mi + (size_t)s_dst[e]*HID + 4*q;
        red_add_v4(dstp, mrow[0]*se, mrow[1]*se, mrow[2]*se, mrow[3]*se);
    }
    // ---- scatter: dx[dst] += rel_x/(d+1) * xg ----
    if (tid < TE){
        const float fac = s_g[tid] / (s_d[tid] + 1.0f);
        const int dst = s_dst[tid];
#pragma unroll
        for (int c=0;c<3;c++)
            atomicAdd(&g_dx[(size_t)dst*3+c], s_rel[tid*3+c]*fac);
    }
}

__global__ __launch_bounds__(NT, 1)
void node_kernel(const float* __restrict__ h, const float* __restrict__ x,
                 const float* __restrict__ mask,
                 const float* __restrict__ Wn1, const float* __restrict__ bn1,
                 const float* __restrict__ Wn2, const float* __restrict__ bn2,
                 float* __restrict__ out_h, float* __restrict__ out_x, int N)
{
    extern __shared__ float smf[];
    float* s_nz = smf;                 // TN*NZS
    float* buf0 = s_nz + TN*NZS;       // BUF_F
    float* buf1 = buf0 + BUF_F;        // BUF_F
    float* s_a  = buf1 + BUF_F;        // TN*MS
    const int tid = threadIdx.x, n0 = blockIdx.x*TN;

    stage_chunk(buf0, Wn1, KC*32, tid); CP_COMMIT();
    for (int idx = tid; idx < TN*32; idx += NT){
        const int r = idx>>5, q = idx&31, n = n0+r;
        float4 vm = make_float4(0.f,0.f,0.f,0.f), vh = vm;
        if (n < N){
            vm = *(const float4*)(g_mi+(size_t)n*HID+4*q);
            vh = *(const float4*)(h+(size_t)n*HID+4*q);
        }
        *(float4*)(s_nz + r*NZS + 4*q) = vm;
        *(float4*)(s_nz + r*NZS + HID + 4*q) = vh;
    }
    gemm_pipe<2*HID, NZS, true, 0>(s_nz, Wn1, bn1, s_a, MS, buf0, buf1, tid);
    // NC=8: last chunk computed from buf1 -> buf0 free
    stage_chunk(buf0, Wn2, KC*32, tid); CP_COMMIT();
    gemm_pipe<HID, MS, false, 0>(s_a, Wn2, bn2, s_nz, NZS, buf0, buf1, tid);
    __syncthreads();

    for (int idx = tid; idx < TN*32; idx += NT){
        const int r = idx>>5, q = idx&31, n = n0+r;
        if (n < N){
            const float4 vh = *(const float4*)(h+(size_t)n*HID+4*q);
            const float4 vr = *(const float4*)(s_nz + r*NZS + 4*q);
            *(float4*)(out_h+(size_t)n*HID+4*q) =
                make_float4(vh.x+vr.x, vh.y+vr.y, vh.z+vr.z, vh.w+vr.w);
        }
    }
    if (tid < TN){
        const int n = n0 + tid;
        if (n < N){
            const float m = mask[n];
#pragma unroll
            for (int c=0;c<3;c++)
                out_x[(size_t)n*3+c] = x[(size_t)n*3+c] + g_dx[(size_t)n*3+c]*m;
        }
    }
}

extern "C" void kernel_launch(void* const* d_in, const int* in_sizes, int n_in,
                              void* d_out, int out_size)
{
    const float* h     = (const float*)d_in[0];
    const float* x     = (const float*)d_in[1];
    const int*   eidx  = (const int*)d_in[2];   // int32 (JAX x64 disabled)
    const float* mask  = (const float*)d_in[3];
    const float* eattr = (const float*)d_in[4];
    const float* We1   = (const float*)d_in[5];
    const float* be1   = (const float*)d_in[6];
    const float* We2   = (const float*)d_in[7];
    const float* be2   = (const float*)d_in[8];
    const float* Winf  = (const float*)d_in[9];
    const float* binf  = (const float*)d_in[10];
    const float* Wx1   = (const float*)d_in[11];
    const float* bx1   = (const float*)d_in[12];
    const float* Wx2   = (const float*)d_in[13];
    const float* Wn1   = (const float*)d_in[14];
    const float* bn1   = (const float*)d_in[15];
    const float* Wn2   = (const float*)d_in[16];
    const float* bn2   = (const float*)d_in[17];

    const int N = in_sizes[0] / HID;
    const int E = in_sizes[2] / 2;
    float* out_h = (float*)d_out;
    float* out_x = (float*)d_out + (size_t)N * HID;

    void *mi_ptr = nullptr, *dx_ptr = nullptr;
    cudaGetSymbolAddress(&mi_ptr, g_mi);
    cudaGetSymbolAddress(&dx_ptr, g_dx);
    zero_kernel<<<592, 256>>>((float*)mi_ptr, N * HID);
    zero_kernel<<<64, 256>>>((float*)dx_ptr, N * 3);

    const size_t pre_smem  = (size_t)PRE_SMEM_F  * sizeof(float);
    const size_t edge_smem = (size_t)EDGE_SMEM_F * sizeof(float);
    const size_t node_smem = (size_t)NODE_SMEM_F * sizeof(float);
    cudaFuncSetAttribute(pre_kernel,  cudaFuncAttributeMaxDynamicSharedMemorySize, (int)pre_smem);
    cudaFuncSetAttribute(edge_kernel, cudaFuncAttributeMaxDynamicSharedMemorySize, (int)edge_smem);
    cudaFuncSetAttribute(node_kernel, cudaFuncAttributeMaxDynamicSharedMemorySize, (int)node_smem);

    const int nb = (N + TN - 1) / TN;
    pre_kernel<<<nb, NT, pre_smem>>>(h, We1, N);

    const int eb = (E + TE - 1) / TE;
    edge_kernel<<<eb, NT, edge_smem>>>(x, eidx, eattr, We1, be1, We2, be2,
                                       Winf, binf, Wx1, bx1, Wx2, E);

    node_kernel<<<nb, NT, node_smem>>>(h, x, mask, Wn1, bn1, Wn2, bn2,
                                       out_h, out_x, N);
}